// round 15
// baseline (speedup 1.0000x reference)
#include <cuda_runtime.h>
#include <cuda_bf16.h>
#include <cstdint>

// Problem constants
#define BATCH   2
#define SEQ     2048
#define NHEADS  16
#define DHEAD   64
#define DMODEL  1024
#define ATTN_SCALE_INV 0.125f
#define LOG2E 1.4426950408889634f

// bf16 hi/lo split operand buffers
__device__ __nv_bfloat16 g_ahi[BATCH * SEQ * DMODEL];   // z hi  [M=4096, K=1024]
__device__ __nv_bfloat16 g_alo[BATCH * SEQ * DMODEL];   // z lo
__device__ __nv_bfloat16 g_bhi[DMODEL * DMODEL];        // W_O^T hi [N=1024, K=1024]
__device__ __nv_bfloat16 g_blo[DMODEL * DMODEL];        // W_O^T lo
// Pre-converted K: [b,h,kpos,d], V transposed: [b,h,d,kpos]
__device__ __nv_bfloat16 g_khi[BATCH * NHEADS * SEQ * DHEAD];
__device__ __nv_bfloat16 g_klo[BATCH * NHEADS * SEQ * DHEAD];
__device__ __nv_bfloat16 g_vthi[BATCH * NHEADS * DHEAD * SEQ];
__device__ __nv_bfloat16 g_vtlo[BATCH * NHEADS * DHEAD * SEQ];

// ---------------------------------------------------------------------------
// PTX helpers
// ---------------------------------------------------------------------------
__device__ __forceinline__ void mma16816(float* c, const uint32_t* a, const uint32_t* b)
{
    asm volatile(
        "mma.sync.aligned.m16n8k16.row.col.f32.bf16.bf16.f32 "
        "{%0,%1,%2,%3}, {%4,%5,%6,%7}, {%8,%9}, {%0,%1,%2,%3};"
        : "+f"(c[0]), "+f"(c[1]), "+f"(c[2]), "+f"(c[3])
        : "r"(a[0]), "r"(a[1]), "r"(a[2]), "r"(a[3]), "r"(b[0]), "r"(b[1]));
}

__device__ __forceinline__ void ldsm4(uint32_t* r, uint32_t addr)
{
    asm volatile("ldmatrix.sync.aligned.m8n8.x4.shared.b16 {%0,%1,%2,%3}, [%4];"
                 : "=r"(r[0]), "=r"(r[1]), "=r"(r[2]), "=r"(r[3]) : "r"(addr));
}

__device__ __forceinline__ uint32_t smem_u32(const void* p) {
    uint32_t a;
    asm("{ .reg .u64 t; cvta.to.shared.u64 t, %1; cvt.u32.u64 %0, t; }"
        : "=r"(a) : "l"(p));
    return a;
}

__device__ __forceinline__ float ex2(float x) {
    float r;
    asm("ex2.approx.f32 %0, %1;" : "=f"(r) : "f"(x));
    return r;
}

#define CP_ASYNC16(dst, src) \
    asm volatile("cp.async.cg.shared.global [%0], [%1], 16;" :: "r"(dst), "l"(src))
#define CP_COMMIT() asm volatile("cp.async.commit_group;" ::: "memory")
#define CP_WAIT0()  asm volatile("cp.async.wait_group 0;" ::: "memory")
#define CP_WAIT1()  asm volatile("cp.async.wait_group 1;" ::: "memory")

__device__ __forceinline__ void split2(float a, float b, uint32_t& hi, uint32_t& lo)
{
    __nv_bfloat162 h2 = __floats2bfloat162_rn(a, b);
    float ra = a - __bfloat162float(h2.x);
    float rb = b - __bfloat162float(h2.y);
    __nv_bfloat162 l2 = __floats2bfloat162_rn(ra, rb);
    hi = *(uint32_t*)&h2;
    lo = *(uint32_t*)&l2;
}

// ---------------------------------------------------------------------------
// Merged pre-pass
// ---------------------------------------------------------------------------
#define PRE_COPY_B   4096
#define PRE_W_B      1024
#define PRE_K_B      8192
#define PRE_V_B      4096
#define PRE_TOTAL_B  (PRE_COPY_B + PRE_W_B + PRE_K_B + PRE_V_B)

__global__ __launch_bounds__(256)
void prepass_kernel(const float* __restrict__ residual, float* __restrict__ dst,
                    const float* __restrict__ W,
                    const float* __restrict__ k,
                    const float* __restrict__ v)
{
    __shared__ float tile[32][33];
    const int bid = blockIdx.x;
    const int t   = threadIdx.x;

    if (bid < PRE_COPY_B) {
        int i = bid * 256 + t;
        ((float4*)dst)[i] = ((const float4*)residual)[i];
        return;
    }
    if (bid < PRE_COPY_B + PRE_W_B) {
        const int id = bid - PRE_COPY_B;
        const int bx = (id & 31) * 32;
        const int by = (id >> 5) * 32;
        const int tx = t & 31;
        const int ty = t >> 5;
        #pragma unroll
        for (int r = 0; r < 32; r += 8)
            tile[ty + r][tx] = W[(size_t)(by + ty + r) * DMODEL + bx + tx];
        __syncthreads();
        #pragma unroll
        for (int r = 0; r < 32; r += 8) {
            float f = tile[tx][ty + r];
            int n = bx + ty + r, kk = by + tx;
            __nv_bfloat16 h = __float2bfloat16(f);
            __nv_bfloat16 l = __float2bfloat16(f - __bfloat162float(h));
            g_bhi[(size_t)n * DMODEL + kk] = h;
            g_blo[(size_t)n * DMODEL + kk] = l;
        }
        return;
    }
    if (bid < PRE_COPY_B + PRE_W_B + PRE_K_B) {
        const int i = (bid - PRE_COPY_B - PRE_W_B) * 256 + t;
        const int d2 = i & 31;
        const int h  = (i >> 5) & 15;
        const int s  = (i >> 9) & 2047;
        const int b  = i >> 20;
        float2 f = *(const float2*)(k + ((size_t)(b * SEQ + s) * DMODEL) + h * DHEAD + d2 * 2);
        uint32_t hi, lo;
        split2(f.x, f.y, hi, lo);
        const size_t o = (((size_t)(b * NHEADS + h) * SEQ) + s) * DHEAD + d2 * 2;
        *(uint32_t*)(g_khi + o) = hi;
        *(uint32_t*)(g_klo + o) = lo;
        return;
    }
    {
        const int id = bid - PRE_COPY_B - PRE_W_B - PRE_K_B;
        const int ktb = (id & 63) * 32;
        const int dtb = ((id >> 6) & 1) * 32;
        const int bh  = id >> 7;
        const int b   = bh >> 4, h = bh & 15;
        const int tx = t & 31;
        const int ty = t >> 5;
        #pragma unroll
        for (int r = 0; r < 32; r += 8)
            tile[ty + r][tx] = v[(size_t)(b * SEQ + ktb + ty + r) * DMODEL + h * DHEAD + dtb + tx];
        __syncthreads();
        #pragma unroll
        for (int r = 0; r < 32; r += 8) {
            float f = tile[tx][ty + r];
            const int d = dtb + ty + r, kp = ktb + tx;
            __nv_bfloat16 hh = __float2bfloat16(f);
            __nv_bfloat16 ll = __float2bfloat16(f - __bfloat162float(hh));
            const size_t o = ((size_t)(bh * DHEAD + d) * SEQ) + kp;
            g_vthi[o] = hh;
            g_vtlo[o] = ll;
        }
    }
}

// ---------------------------------------------------------------------------
// Tensor-core flash attention v3: 512 threads / 16 warps, 256 q-rows per CTA,
// warp tile 16 rows x 64-wide K-tiles, 3-stage cp.async, Q-lo in SMEM,
// softmax in log2 domain. Warps inactive for a tile skip straight to barrier.
// ---------------------------------------------------------------------------
#define KTILE  64
#define KROWP  72
#define ST_KH  0
#define ST_KL  9216
#define ST_VH  18432
#define ST_VL  27648
#define ASTG   36864                     // bytes per stage
#define QLO_OFF (3 * ASTG)               // 110592
#define ATT_SMEM (QLO_OFF + 256 * KROWP * 2)   // 147456

__global__ __launch_bounds__(512, 1)
void attn_tc_kernel(const float* __restrict__ q)
{
    extern __shared__ __align__(16) char smem[];
    const uint32_t sbase = smem_u32(smem);

    const int b   = blockIdx.z;
    const int h   = blockIdx.y;
    const int bh  = b * NHEADS + h;
    const int qt  = (int)(gridDim.x - 1) - (int)blockIdx.x;   // 0..7, big first
    const int tid = threadIdx.x;
    const int wid = tid >> 5;           // 0..15
    const int lane = tid & 31;
    const int g   = lane >> 2;
    const int t2  = (lane & 3) * 2;
    const int wm  = wid * 16;           // warp row offset in CTA (0..240)
    const int rowbase = qt * 256 + wm;  // global first row of this warp

    const __nv_bfloat16* kh_g = g_khi + (size_t)bh * SEQ * DHEAD;
    const __nv_bfloat16* kl_g = g_klo + (size_t)bh * SEQ * DHEAD;
    const __nv_bfloat16* vh_g = g_vthi + (size_t)bh * DHEAD * SEQ;
    const __nv_bfloat16* vl_g = g_vtlo + (size_t)bh * DHEAD * SEQ;

    const uint32_t offK = (uint32_t)(((lane & 7) + ((lane >> 4) & 1) * 8) * KROWP
                                     + ((lane >> 3) & 1) * 8);
    const uint32_t offQ = (uint32_t)(((lane & 7) + ((lane >> 3) & 1) * 8) * KROWP
                                     + ((lane >> 4) & 1) * 8);

    const float qsc = ATTN_SCALE_INV * LOG2E;
    const float* qb = q + (size_t)b * SEQ * DMODEL + h * DHEAD;

    // ---- Q-lo (scaled residuals) into SMEM, cooperative over 512 threads ----
    for (int idx = tid; idx < 256 * 16; idx += 512) {
        int row = idx >> 4, c4 = (idx & 15) * 4;
        float4 f = *(const float4*)(qb + (size_t)(qt * 256 + row) * DMODEL + c4);
        uint32_t h0, l0_, h1, l1_;
        split2(f.x * qsc, f.y * qsc, h0, l0_);
        split2(f.z * qsc, f.w * qsc, h1, l1_);
        *(uint2*)(smem + QLO_OFF + (row * KROWP + c4) * 2) = make_uint2(l0_, l1_);
        (void)h0; (void)h1;
    }

    // ---- Q-hi fragments in registers ----
    uint32_t qh[4][4];
    #pragma unroll
    for (int kc = 0; kc < 4; kc++) {
        #pragma unroll
        for (int a = 0; a < 4; a++) {
            int row = rowbase + g + ((a & 1) ? 8 : 0);
            int col = kc * 16 + t2 + ((a >= 2) ? 8 : 0);
            float2 f = *(const float2*)(qb + (size_t)row * DMODEL + col);
            uint32_t hi, lo;
            split2(f.x * qsc, f.y * qsc, hi, lo);
            qh[kc][a] = hi;
        }
    }

    float oacc[8][4];
    #pragma unroll
    for (int nt = 0; nt < 8; nt++)
        #pragma unroll
        for (int r = 0; r < 4; r++) oacc[nt][r] = 0.f;
    float m0 = -1e30f, m1 = -1e30f, l0 = 0.f, l1 = 0.f;

    // Per tile: 512 threads x (K hi+lo, V hi+lo) = 4 x 16B each
    auto issue_tile = [&](int tt, int stage) {
        const uint32_t sb = sbase + (uint32_t)stage * ASTG;
        const int row = tid >> 3, seg = tid & 7;
        const uint32_t do_ = (uint32_t)(row * KROWP + seg * 8) * 2;
        const size_t gk = (size_t)(tt * KTILE + row) * DHEAD + seg * 8;
        CP_ASYNC16(sb + ST_KH + do_, kh_g + gk);
        CP_ASYNC16(sb + ST_KL + do_, kl_g + gk);
        const size_t gv = (size_t)row * SEQ + tt * KTILE + seg * 8;
        CP_ASYNC16(sb + ST_VH + do_, vh_g + gv);
        CP_ASYNC16(sb + ST_VL + do_, vl_g + gv);
    };

    const int ntiles = 4 * (qt + 1);
    issue_tile(0, 0);
    CP_COMMIT();
    issue_tile(1, 1);
    CP_COMMIT();

    for (int kt = 0; kt < ntiles; kt++) {
        const uint32_t sb = sbase + (uint32_t)(kt % 3) * ASTG;
        CP_WAIT1();
        __syncthreads();   // stage kt visible; all warps done with stage kt-1; Qlo ready (kt=0)

        const int kb = kt * KTILE;
        if (kb <= rowbase + 15) {   // warp has unmasked rows in this tile
            // ---- S = Q @ K^T (3-term split) ----
            float sacc[8][4];
            #pragma unroll
            for (int nt = 0; nt < 8; nt++)
                #pragma unroll
                for (int r = 0; r < 4; r++) sacc[nt][r] = 0.f;

            #pragma unroll
            for (int kc = 0; kc < 4; kc++) {
                uint32_t qlf[4];
                ldsm4(qlf, sbase + QLO_OFF + (uint32_t)(wm * KROWP + kc * 16 + offQ) * 2);
                #pragma unroll
                for (int ntp = 0; ntp < 4; ntp++) {
                    const uint32_t rel = (uint32_t)(ntp * 16 * KROWP + kc * 16 + offK) * 2;
                    uint32_t bh2[4], bl2[4];
                    ldsm4(bh2, sb + ST_KH + rel);
                    ldsm4(bl2, sb + ST_KL + rel);
                    mma16816(sacc[2*ntp],   qh[kc], bh2);
                    mma16816(sacc[2*ntp],   qh[kc], bl2);
                    mma16816(sacc[2*ntp],   qlf,    bh2);
                    mma16816(sacc[2*ntp+1], qh[kc], bh2 + 2);
                    mma16816(sacc[2*ntp+1], qh[kc], bl2 + 2);
                    mma16816(sacc[2*ntp+1], qlf,    bh2 + 2);
                }
            }

            // ---- causal mask (boundary tiles only) ----
            if (kb + 63 > rowbase) {
                const int rl0 = rowbase + g, rl1 = rl0 + 8;
                #pragma unroll
                for (int nt = 0; nt < 8; nt++) {
                    int c0 = kb + nt * 8 + t2;
                    if (c0     > rl0) sacc[nt][0] = -1e30f;
                    if (c0 + 1 > rl0) sacc[nt][1] = -1e30f;
                    if (c0     > rl1) sacc[nt][2] = -1e30f;
                    if (c0 + 1 > rl1) sacc[nt][3] = -1e30f;
                }
            }

            // ---- online softmax (log2 domain) ----
            float mx0 = -1e30f, mx1 = -1e30f;
            #pragma unroll
            for (int nt = 0; nt < 8; nt++) {
                mx0 = fmaxf(mx0, fmaxf(sacc[nt][0], sacc[nt][1]));
                mx1 = fmaxf(mx1, fmaxf(sacc[nt][2], sacc[nt][3]));
            }
            mx0 = fmaxf(mx0, __shfl_xor_sync(0xffffffffu, mx0, 1));
            mx0 = fmaxf(mx0, __shfl_xor_sync(0xffffffffu, mx0, 2));
            mx1 = fmaxf(mx1, __shfl_xor_sync(0xffffffffu, mx1, 1));
            mx1 = fmaxf(mx1, __shfl_xor_sync(0xffffffffu, mx1, 2));

            float mn0 = fmaxf(m0, mx0), mn1 = fmaxf(m1, mx1);
            float c0 = ex2(m0 - mn0), c1 = ex2(m1 - mn1);
            m0 = mn0; m1 = mn1;
            l0 *= c0; l1 *= c1;
            #pragma unroll
            for (int nt = 0; nt < 8; nt++) {
                oacc[nt][0] *= c0; oacc[nt][1] *= c0;
                oacc[nt][2] *= c1; oacc[nt][3] *= c1;
            }

            float ls0 = 0.f, ls1 = 0.f;
            #pragma unroll
            for (int nt = 0; nt < 8; nt++) {
                float p0 = ex2(sacc[nt][0] - m0);
                float p1 = ex2(sacc[nt][1] - m0);
                float p2 = ex2(sacc[nt][2] - m1);
                float p3 = ex2(sacc[nt][3] - m1);
                sacc[nt][0] = p0; sacc[nt][1] = p1;
                sacc[nt][2] = p2; sacc[nt][3] = p3;
                ls0 += p0 + p1; ls1 += p2 + p3;
            }
            l0 += ls0; l1 += ls1;

            // ---- O += P @ V (3-term split) ----
            #pragma unroll
            for (int kc = 0; kc < 4; kc++) {
                uint32_t ah[4], al[4];
                split2(sacc[2*kc][0],   sacc[2*kc][1],   ah[0], al[0]);
                split2(sacc[2*kc][2],   sacc[2*kc][3],   ah[1], al[1]);
                split2(sacc[2*kc+1][0], sacc[2*kc+1][1], ah[2], al[2]);
                split2(sacc[2*kc+1][2], sacc[2*kc+1][3], ah[3], al[3]);
                #pragma unroll
                for (int ntp = 0; ntp < 4; ntp++) {
                    const uint32_t rel = (uint32_t)(ntp * 16 * KROWP + kc * 16 + offK) * 2;
                    uint32_t vh2[4], vl2[4];
                    ldsm4(vh2, sb + ST_VH + rel);
                    ldsm4(vl2, sb + ST_VL + rel);
                    mma16816(oacc[2*ntp],   ah, vh2);
                    mma16816(oacc[2*ntp],   ah, vl2);
                    mma16816(oacc[2*ntp],   al, vh2);
                    mma16816(oacc[2*ntp+1], ah, vh2 + 2);
                    mma16816(oacc[2*ntp+1], ah, vl2 + 2);
                    mma16816(oacc[2*ntp+1], al, vh2 + 2);
                }
            }
        }

        if (kt + 2 < ntiles) issue_tile(kt + 2, (kt + 2) % 3);
        CP_COMMIT();
    }

    // ---- finalize ----
    l0 += __shfl_xor_sync(0xffffffffu, l0, 1);
    l0 += __shfl_xor_sync(0xffffffffu, l0, 2);
    l1 += __shfl_xor_sync(0xffffffffu, l1, 1);
    l1 += __shfl_xor_sync(0xffffffffu, l1, 2);
    const float inv0 = 1.f / l0, inv1 = 1.f / l1;

    const int r0 = rowbase + g;
    const size_t zo0 = (size_t)(b * SEQ + r0) * DMODEL + h * DHEAD;
    const size_t zo1 = (size_t)(b * SEQ + r0 + 8) * DMODEL + h * DHEAD;
    #pragma unroll
    for (int nt = 0; nt < 8; nt++) {
        const int d = nt * 8 + t2;
        uint32_t zh, zl;
        split2(oacc[nt][0] * inv0, oacc[nt][1] * inv0, zh, zl);
        *(uint32_t*)(g_ahi + zo0 + d) = zh;
        *(uint32_t*)(g_alo + zo0 + d) = zl;
        split2(oacc[nt][2] * inv1, oacc[nt][3] * inv1, zh, zl);
        *(uint32_t*)(g_ahi + zo1 + d) = zh;
        *(uint32_t*)(g_alo + zo1 + d) = zl;
    }
}

// ---------------------------------------------------------------------------
// Tensor-core projection GEMM: CTA 256x128, warp tile 64x64, 3-stage cp.async.
// (R12 configuration — known good.)
// ---------------------------------------------------------------------------
#define TK       32
#define NCHUNK   (DMODEL / TK)        // 32
#define ROWP     40
#define A_BYTES  (256 * ROWP * 2)     // 20480
#define B_BYTES  (128 * ROWP * 2)     // 10240
#define OFF_AH   0
#define OFF_AL   A_BYTES
#define OFF_BH   (2 * A_BYTES)
#define OFF_BL   (2 * A_BYTES + B_BYTES)
#define GSTAGE_BYTES (2 * A_BYTES + 2 * B_BYTES)   // 61440
#define GEMM_SMEM (3 * GSTAGE_BYTES)               // 184320

__global__ __launch_bounds__(256, 1)
void gemm_tc_kernel(const float* __restrict__ bias, float* __restrict__ C)
{
    extern __shared__ __align__(16) char smem[];
    const uint32_t sbase = smem_u32(smem);

    const int tid  = threadIdx.x;
    const int wid  = tid >> 5;
    const int lane = tid & 31;
    const int bm = blockIdx.y * 256;
    const int bn = blockIdx.x * 128;

    const int wm = (wid & 3) * 64;
    const int wn = (wid >> 2) * 64;
    const int g  = lane >> 2;
    const int t2 = (lane & 3) * 2;

    const uint32_t offA = (uint32_t)(((lane & 7) + ((lane >> 3) & 1) * 8) * ROWP
                                     + ((lane >> 4) & 1) * 8);
    const uint32_t offB = (uint32_t)(((lane & 7) + ((lane >> 4) & 1) * 8) * ROWP
                                     + ((lane >> 3) & 1) * 8);

    float acc[4][8][4];
    #pragma unroll
    for (int mt = 0; mt < 4; mt++)
        #pragma unroll
        for (int nt = 0; nt < 8; nt++)
            #pragma unroll
            for (int r = 0; r < 4; r++) acc[mt][nt][r] = 0.f;

    auto issue_chunk = [&](int kc, int stage) {
        const uint32_t sb = sbase + (uint32_t)stage * GSTAGE_BYTES;
        const int kb = kc * TK;
        #pragma unroll
        for (int rep = 0; rep < 4; rep++) {
            int idx = tid + rep * 256;
            int row = idx >> 2, seg = idx & 3;
            uint32_t d = sb + (uint32_t)(row * (ROWP * 2) + seg * 16);
            const size_t ga = (size_t)(bm + row) * DMODEL + kb + seg * 8;
            CP_ASYNC16(d + OFF_AH, g_ahi + ga);
            CP_ASYNC16(d + OFF_AL, g_alo + ga);
        }
        #pragma unroll
        for (int rep = 0; rep < 2; rep++) {
            int idx = tid + rep * 256;
            int row = idx >> 2, seg = idx & 3;
            uint32_t d = sb + (uint32_t)(row * (ROWP * 2) + seg * 16);
            const size_t gb = (size_t)(bn + row) * DMODEL + kb + seg * 8;
            CP_ASYNC16(d + OFF_BH, g_bhi + gb);
            CP_ASYNC16(d + OFF_BL, g_blo + gb);
        }
    };

    issue_chunk(0, 0);
    CP_COMMIT();
    issue_chunk(1, 1);
    CP_COMMIT();

    for (int kc = 0; kc < NCHUNK; kc++) {
        CP_WAIT1();
        __syncthreads();

        const uint32_t sb = sbase + (uint32_t)(kc % 3) * GSTAGE_BYTES;

        #pragma unroll
        for (int ks = 0; ks < 2; ks++) {
            const int k0 = ks * 16;
            uint32_t ah[4][4], al[4][4];
            #pragma unroll
            for (int mt = 0; mt < 4; mt++) {
                const uint32_t rel = (uint32_t)((wm + mt * 16) * ROWP + k0 + offA) * 2;
                ldsm4(ah[mt], sb + OFF_AH + rel);
                ldsm4(al[mt], sb + OFF_AL + rel);
            }
            #pragma unroll
            for (int ng = 0; ng < 4; ng++) {
                const uint32_t rel = (uint32_t)((wn + ng * 16) * ROWP + k0 + offB) * 2;
                uint32_t bh2[4], bl2[4];
                ldsm4(bh2, sb + OFF_BH + rel);
                ldsm4(bl2, sb + OFF_BL + rel);
                #pragma unroll
                for (int mt = 0; mt < 4; mt++) {
                    mma16816(acc[mt][2*ng],   ah[mt], bh2);
                    mma16816(acc[mt][2*ng],   ah[mt], bl2);
                    mma16816(acc[mt][2*ng],   al[mt], bh2);
                    mma16816(acc[mt][2*ng+1], ah[mt], bh2 + 2);
                    mma16816(acc[mt][2*ng+1], ah[mt], bl2 + 2);
                    mma16816(acc[mt][2*ng+1], al[mt], bh2 + 2);
                }
            }
        }

        if (kc + 2 < NCHUNK) issue_chunk(kc + 2, (kc + 2) % 3);
        CP_COMMIT();
    }

    #pragma unroll
    for (int mt = 0; mt < 4; mt++) {
        const int row0 = bm + wm + mt * 16 + g;
        #pragma unroll
        for (int nt = 0; nt < 8; nt++) {
            const int col0 = bn + wn + nt * 8 + t2;
            const float b0 = bias[col0], b1 = bias[col0 + 1];
            float2 o01 = { acc[mt][nt][0] + b0, acc[mt][nt][1] + b1 };
            float2 o23 = { acc[mt][nt][2] + b0, acc[mt][nt][3] + b1 };
            *(float2*)(C + (size_t)row0 * DMODEL + col0) = o01;
            *(float2*)(C + (size_t)(row0 + 8) * DMODEL + col0) = o23;
        }
    }
}

// ---------------------------------------------------------------------------
// Launch
// ---------------------------------------------------------------------------
extern "C" void kernel_launch(void* const* d_in, const int* in_sizes, int n_in,
                              void* d_out, int out_size)
{
    const float* residual = (const float*)d_in[0];
    const float* q        = (const float*)d_in[1];
    const float* k        = (const float*)d_in[2];
    const float* v        = (const float*)d_in[3];
    const float* W_O      = (const float*)d_in[4];
    const float* b_O      = (const float*)d_in[5];

    float* out = (float*)d_out;
    const int res_elems = BATCH * SEQ * DMODEL;

    // Merged pre-pass
    prepass_kernel<<<PRE_TOTAL_B, 256>>>(residual, out, W_O, k, v);

    // Attention v3: 512 threads, 256 q-rows/CTA
    cudaFuncSetAttribute(attn_tc_kernel,
                         cudaFuncAttributeMaxDynamicSharedMemorySize, ATT_SMEM);
    attn_tc_kernel<<<dim3(SEQ / 256, NHEADS, BATCH), 512, ATT_SMEM>>>(q);

    // Projection GEMM (R12 config)
    cudaFuncSetAttribute(gemm_tc_kernel,
                         cudaFuncAttributeMaxDynamicSharedMemorySize, GEMM_SMEM);
    gemm_tc_kernel<<<dim3(DMODEL / 128, (BATCH * SEQ) / 256), 256, GEMM_SMEM>>>(
        b_O, out + res_elems);
}

// round 17
// speedup vs baseline: 1.1367x; 1.1367x over previous
#include <cuda_runtime.h>
#include <cuda_bf16.h>
#include <cstdint>

// Problem constants
#define BATCH   2
#define SEQ     2048
#define NHEADS  16
#define DHEAD   64
#define DMODEL  1024
#define ATTN_SCALE_INV 0.125f
#define LOG2E 1.4426950408889634f

// bf16 hi/lo split operand buffers
__device__ __nv_bfloat16 g_ahi[BATCH * SEQ * DMODEL];   // z hi  [M=4096, K=1024]
__device__ __nv_bfloat16 g_alo[BATCH * SEQ * DMODEL];   // z lo
__device__ __nv_bfloat16 g_bhi[DMODEL * DMODEL];        // W_O^T hi [N=1024, K=1024]
__device__ __nv_bfloat16 g_blo[DMODEL * DMODEL];        // W_O^T lo
// Pre-converted K: [b,h,kpos,d], V transposed: [b,h,d,kpos]
__device__ __nv_bfloat16 g_khi[BATCH * NHEADS * SEQ * DHEAD];
__device__ __nv_bfloat16 g_klo[BATCH * NHEADS * SEQ * DHEAD];
__device__ __nv_bfloat16 g_vthi[BATCH * NHEADS * DHEAD * SEQ];
__device__ __nv_bfloat16 g_vtlo[BATCH * NHEADS * DHEAD * SEQ];

// ---------------------------------------------------------------------------
// PTX helpers
// ---------------------------------------------------------------------------
__device__ __forceinline__ void mma16816(float* c, const uint32_t* a, const uint32_t* b)
{
    asm volatile(
        "mma.sync.aligned.m16n8k16.row.col.f32.bf16.bf16.f32 "
        "{%0,%1,%2,%3}, {%4,%5,%6,%7}, {%8,%9}, {%0,%1,%2,%3};"
        : "+f"(c[0]), "+f"(c[1]), "+f"(c[2]), "+f"(c[3])
        : "r"(a[0]), "r"(a[1]), "r"(a[2]), "r"(a[3]), "r"(b[0]), "r"(b[1]));
}

__device__ __forceinline__ void ldsm4(uint32_t* r, uint32_t addr)
{
    asm volatile("ldmatrix.sync.aligned.m8n8.x4.shared.b16 {%0,%1,%2,%3}, [%4];"
                 : "=r"(r[0]), "=r"(r[1]), "=r"(r[2]), "=r"(r[3]) : "r"(addr));
}

__device__ __forceinline__ uint32_t smem_u32(const void* p) {
    uint32_t a;
    asm("{ .reg .u64 t; cvta.to.shared.u64 t, %1; cvt.u32.u64 %0, t; }"
        : "=r"(a) : "l"(p));
    return a;
}

__device__ __forceinline__ float ex2(float x) {
    float r;
    asm("ex2.approx.f32 %0, %1;" : "=f"(r) : "f"(x));
    return r;
}

#define CP_ASYNC16(dst, src) \
    asm volatile("cp.async.cg.shared.global [%0], [%1], 16;" :: "r"(dst), "l"(src))
#define CP_COMMIT() asm volatile("cp.async.commit_group;" ::: "memory")
#define CP_WAIT0()  asm volatile("cp.async.wait_group 0;" ::: "memory")
#define CP_WAIT1()  asm volatile("cp.async.wait_group 1;" ::: "memory")

__device__ __forceinline__ void split2(float a, float b, uint32_t& hi, uint32_t& lo)
{
    __nv_bfloat162 h2 = __floats2bfloat162_rn(a, b);
    float ra = a - __bfloat162float(h2.x);
    float rb = b - __bfloat162float(h2.y);
    __nv_bfloat162 l2 = __floats2bfloat162_rn(ra, rb);
    hi = *(uint32_t*)&h2;
    lo = *(uint32_t*)&l2;
}

// ---------------------------------------------------------------------------
// Merged pre-pass: one kernel, four roles by block range.
// ---------------------------------------------------------------------------
#define PRE_COPY_B   4096
#define PRE_W_B      1024
#define PRE_K_B      4096
#define PRE_V_B      4096
#define PRE_TOTAL_B  (PRE_COPY_B + PRE_W_B + PRE_K_B + PRE_V_B)

__global__ __launch_bounds__(256)
void prepass_kernel(const float* __restrict__ residual, float* __restrict__ dst,
                    const float* __restrict__ W,
                    const float* __restrict__ k,
                    const float* __restrict__ v)
{
    __shared__ float tile[32][33];
    const int bid = blockIdx.x;
    const int t   = threadIdx.x;

    if (bid < PRE_COPY_B) {
        int i = bid * 256 + t;
        ((float4*)dst)[i] = ((const float4*)residual)[i];
        return;
    }
    if (bid < PRE_COPY_B + PRE_W_B) {
        const int id = bid - PRE_COPY_B;
        const int bx = (id & 31) * 32;
        const int by = (id >> 5) * 32;
        const int tx = t & 31;
        const int ty = t >> 5;
        #pragma unroll
        for (int r = 0; r < 32; r += 8)
            tile[ty + r][tx] = W[(size_t)(by + ty + r) * DMODEL + bx + tx];
        __syncthreads();
        #pragma unroll
        for (int r = 0; r < 32; r += 8) {
            float f = tile[tx][ty + r];
            int n = bx + ty + r, kk = by + tx;
            __nv_bfloat16 h = __float2bfloat16(f);
            __nv_bfloat16 l = __float2bfloat16(f - __bfloat162float(h));
            g_bhi[(size_t)n * DMODEL + kk] = h;
            g_blo[(size_t)n * DMODEL + kk] = l;
        }
        return;
    }
    if (bid < PRE_COPY_B + PRE_W_B + PRE_K_B) {
        // K split (float4): [B,S,H*D] fp32 -> [B,H,S,D] bf16 hi/lo
        const int i = (bid - PRE_COPY_B - PRE_W_B) * 256 + t;   // over B*S*H*D/4
        const int d4 = i & 15;
        const int h  = (i >> 4) & 15;
        const int s  = (i >> 8) & 2047;
        const int b  = i >> 19;
        float4 f = *(const float4*)(k + ((size_t)(b * SEQ + s) * DMODEL) + h * DHEAD + d4 * 4);
        uint32_t h0, l0, h1, l1;
        split2(f.x, f.y, h0, l0);
        split2(f.z, f.w, h1, l1);
        const size_t o = (((size_t)(b * NHEADS + h) * SEQ) + s) * DHEAD + d4 * 4;
        *(uint2*)(g_khi + o) = make_uint2(h0, h1);
        *(uint2*)(g_klo + o) = make_uint2(l0, l1);
        return;
    }
    {
        const int id = bid - PRE_COPY_B - PRE_W_B - PRE_K_B;
        const int ktb = (id & 63) * 32;
        const int dtb = ((id >> 6) & 1) * 32;
        const int bh  = id >> 7;
        const int b   = bh >> 4, h = bh & 15;
        const int tx = t & 31;
        const int ty = t >> 5;
        #pragma unroll
        for (int r = 0; r < 32; r += 8)
            tile[ty + r][tx] = v[(size_t)(b * SEQ + ktb + ty + r) * DMODEL + h * DHEAD + dtb + tx];
        __syncthreads();
        #pragma unroll
        for (int r = 0; r < 32; r += 8) {
            float f = tile[tx][ty + r];
            const int d = dtb + ty + r, kp = ktb + tx;
            __nv_bfloat16 hh = __float2bfloat16(f);
            __nv_bfloat16 ll = __float2bfloat16(f - __bfloat162float(hh));
            const size_t o = ((size_t)(bh * DHEAD + d) * SEQ) + kp;
            g_vthi[o] = hh;
            g_vtlo[o] = ll;
        }
    }
}

// ---------------------------------------------------------------------------
// Tensor-core flash attention: 3-stage cp.async pipeline, ldmatrix frags,
// softmax in log2 domain. Grid: (qtile reversed, h, b). 8 warps x 16 q-rows.
// ---------------------------------------------------------------------------
#define KROWP 72
#define VROWP 136
#define ST_KH  0
#define ST_KL  9216
#define ST_VTH 18432
#define ST_VTL 27136
#define STAGE_BF 35840
#define ATT_SMEM (3 * STAGE_BF * 2)   // 215040 bytes

__global__ __launch_bounds__(256, 1)
void attn_tc_kernel(const float* __restrict__ q)
{
    extern __shared__ __align__(16) char smem[];
    const uint32_t sbase = smem_u32(smem);

    const int b   = blockIdx.z;
    const int h   = blockIdx.y;
    const int bh  = b * NHEADS + h;
    const int qt  = (int)(gridDim.x - 1) - (int)blockIdx.x;
    const int tid = threadIdx.x;
    const int wid = tid >> 5;
    const int lane = tid & 31;
    const int g   = lane >> 2;
    const int t2  = (lane & 3) * 2;
    const int wm  = wid * 16;

    const __nv_bfloat16* kh_g = g_khi + (size_t)bh * SEQ * DHEAD;
    const __nv_bfloat16* kl_g = g_klo + (size_t)bh * SEQ * DHEAD;
    const __nv_bfloat16* vh_g = g_vthi + (size_t)bh * DHEAD * SEQ;
    const __nv_bfloat16* vl_g = g_vtlo + (size_t)bh * DHEAD * SEQ;

    const uint32_t offK = (uint32_t)(((lane & 7) + ((lane >> 4) & 1) * 8) * KROWP
                                     + ((lane >> 3) & 1) * 8);
    const uint32_t offV = (uint32_t)(((lane & 7) + ((lane >> 4) & 1) * 8) * VROWP
                                     + ((lane >> 3) & 1) * 8);

    // ---- Q fragments (pre-scaled by 1/sqrt(d) * log2(e), hi/lo split) ----
    uint32_t qh[4][4], ql[4][4];
    {
        const float qsc = ATTN_SCALE_INV * LOG2E;
        const float* qb = q + (size_t)b * SEQ * DMODEL + h * DHEAD;
        const int r0 = qt * 128 + wm + g;
        #pragma unroll
        for (int kc = 0; kc < 4; kc++) {
            #pragma unroll
            for (int a = 0; a < 4; a++) {
                int row = r0 + ((a & 1) ? 8 : 0);
                int col = kc * 16 + t2 + ((a >= 2) ? 8 : 0);
                float2 f = *(const float2*)(qb + (size_t)row * DMODEL + col);
                split2(f.x * qsc, f.y * qsc, qh[kc][a], ql[kc][a]);
            }
        }
    }

    float oacc[8][4];
    #pragma unroll
    for (int nt = 0; nt < 8; nt++)
        #pragma unroll
        for (int r = 0; r < 4; r++) oacc[nt][r] = 0.f;
    float m0 = -1e30f, m1 = -1e30f, l0 = 0.f, l1 = 0.f;

    auto issue_tile = [&](int tt, int stage) {
        const uint32_t sb = sbase + (uint32_t)stage * (STAGE_BF * 2);
        #pragma unroll
        for (int rep = 0; rep < 4; rep++) {
            int idx = tid + rep * 256;
            int row = idx >> 3, seg = idx & 7;
            const size_t go = (size_t)(tt * 128 + row) * DHEAD + seg * 8;
            uint32_t dst = sb + (uint32_t)(row * KROWP + seg * 8) * 2;
            CP_ASYNC16(dst + ST_KH * 2, kh_g + go);
            CP_ASYNC16(dst + ST_KL * 2, kl_g + go);
        }
        #pragma unroll
        for (int rep = 0; rep < 4; rep++) {
            int idx = tid + rep * 256;
            int row = idx >> 4, seg = idx & 15;
            const size_t go = (size_t)row * SEQ + tt * 128 + seg * 8;
            uint32_t dst = sb + (uint32_t)(row * VROWP + seg * 8) * 2;
            CP_ASYNC16(dst + ST_VTH * 2, vh_g + go);
            CP_ASYNC16(dst + ST_VTL * 2, vl_g + go);
        }
    };

    issue_tile(0, 0);
    CP_COMMIT();
    if (qt >= 1) issue_tile(1, 1);
    CP_COMMIT();

    for (int kt = 0; kt <= qt; kt++) {
        const uint32_t sb = sbase + (uint32_t)(kt % 3) * (STAGE_BF * 2);
        CP_WAIT1();
        __syncthreads();

        // ---- S = Q @ K^T (3-term split) ----
        float sacc[16][4];
        #pragma unroll
        for (int ntp = 0; ntp < 8; ntp++) {
            sacc[2*ntp][0] = sacc[2*ntp][1] = sacc[2*ntp][2] = sacc[2*ntp][3] = 0.f;
            sacc[2*ntp+1][0] = sacc[2*ntp+1][1] = sacc[2*ntp+1][2] = sacc[2*ntp+1][3] = 0.f;
            #pragma unroll
            for (int kc = 0; kc < 4; kc++) {
                const uint32_t rel = (uint32_t)(ntp * 16 * KROWP + kc * 16 + offK) * 2;
                uint32_t bh2[4], bl2[4];
                ldsm4(bh2, sb + ST_KH * 2 + rel);
                ldsm4(bl2, sb + ST_KL * 2 + rel);
                mma16816(sacc[2*ntp],   qh[kc], bh2);
                mma16816(sacc[2*ntp],   qh[kc], bl2);
                mma16816(sacc[2*ntp],   ql[kc], bh2);
                mma16816(sacc[2*ntp+1], qh[kc], bh2 + 2);
                mma16816(sacc[2*ntp+1], qh[kc], bl2 + 2);
                mma16816(sacc[2*ntp+1], ql[kc], bh2 + 2);
            }
        }

        // ---- causal mask (diagonal tile only) ----
        if (kt == qt) {
            const int rl0 = wm + g, rl1 = rl0 + 8;
            #pragma unroll
            for (int nt = 0; nt < 16; nt++) {
                int c0 = nt * 8 + t2;
                if (c0     > rl0) sacc[nt][0] = -1e30f;
                if (c0 + 1 > rl0) sacc[nt][1] = -1e30f;
                if (c0     > rl1) sacc[nt][2] = -1e30f;
                if (c0 + 1 > rl1) sacc[nt][3] = -1e30f;
            }
        }

        // ---- online softmax (log2 domain) ----
        float mx0 = -1e30f, mx1 = -1e30f;
        #pragma unroll
        for (int nt = 0; nt < 16; nt++) {
            mx0 = fmaxf(mx0, fmaxf(sacc[nt][0], sacc[nt][1]));
            mx1 = fmaxf(mx1, fmaxf(sacc[nt][2], sacc[nt][3]));
        }
        mx0 = fmaxf(mx0, __shfl_xor_sync(0xffffffffu, mx0, 1));
        mx0 = fmaxf(mx0, __shfl_xor_sync(0xffffffffu, mx0, 2));
        mx1 = fmaxf(mx1, __shfl_xor_sync(0xffffffffu, mx1, 1));
        mx1 = fmaxf(mx1, __shfl_xor_sync(0xffffffffu, mx1, 2));

        float mn0 = fmaxf(m0, mx0), mn1 = fmaxf(m1, mx1);
        float c0 = ex2(m0 - mn0), c1 = ex2(m1 - mn1);
        m0 = mn0; m1 = mn1;
        l0 *= c0; l1 *= c1;
        #pragma unroll
        for (int nt = 0; nt < 8; nt++) {
            oacc[nt][0] *= c0; oacc[nt][1] *= c0;
            oacc[nt][2] *= c1; oacc[nt][3] *= c1;
        }

        float ls0 = 0.f, ls1 = 0.f;
        #pragma unroll
        for (int nt = 0; nt < 16; nt++) {
            float p0 = ex2(sacc[nt][0] - m0);
            float p1 = ex2(sacc[nt][1] - m0);
            float p2 = ex2(sacc[nt][2] - m1);
            float p3 = ex2(sacc[nt][3] - m1);
            sacc[nt][0] = p0; sacc[nt][1] = p1;
            sacc[nt][2] = p2; sacc[nt][3] = p3;
            ls0 += p0 + p1; ls1 += p2 + p3;
        }
        l0 += ls0; l1 += ls1;

        // ---- O += P @ V (3-term split) ----
        #pragma unroll
        for (int kc = 0; kc < 8; kc++) {
            uint32_t ah[4], al[4];
            split2(sacc[2*kc][0],   sacc[2*kc][1],   ah[0], al[0]);
            split2(sacc[2*kc][2],   sacc[2*kc][3],   ah[1], al[1]);
            split2(sacc[2*kc+1][0], sacc[2*kc+1][1], ah[2], al[2]);
            split2(sacc[2*kc+1][2], sacc[2*kc+1][3], ah[3], al[3]);
            #pragma unroll
            for (int ntp = 0; ntp < 4; ntp++) {
                const uint32_t rel = (uint32_t)(ntp * 16 * VROWP + kc * 16 + offV) * 2;
                uint32_t bh2[4], bl2[4];
                ldsm4(bh2, sb + ST_VTH * 2 + rel);
                ldsm4(bl2, sb + ST_VTL * 2 + rel);
                mma16816(oacc[2*ntp],   ah, bh2);
                mma16816(oacc[2*ntp],   ah, bl2);
                mma16816(oacc[2*ntp],   al, bh2);
                mma16816(oacc[2*ntp+1], ah, bh2 + 2);
                mma16816(oacc[2*ntp+1], ah, bl2 + 2);
                mma16816(oacc[2*ntp+1], al, bh2 + 2);
            }
        }

        if (kt + 2 <= qt) issue_tile(kt + 2, (kt + 2) % 3);
        CP_COMMIT();
    }

    // ---- finalize ----
    l0 += __shfl_xor_sync(0xffffffffu, l0, 1);
    l0 += __shfl_xor_sync(0xffffffffu, l0, 2);
    l1 += __shfl_xor_sync(0xffffffffu, l1, 1);
    l1 += __shfl_xor_sync(0xffffffffu, l1, 2);
    const float inv0 = 1.f / l0, inv1 = 1.f / l1;

    const int r0 = qt * 128 + wm + g;
    const size_t zo0 = (size_t)(b * SEQ + r0) * DMODEL + h * DHEAD;
    const size_t zo1 = (size_t)(b * SEQ + r0 + 8) * DMODEL + h * DHEAD;
    #pragma unroll
    for (int nt = 0; nt < 8; nt++) {
        const int d = nt * 8 + t2;
        uint32_t zh, zl;
        split2(oacc[nt][0] * inv0, oacc[nt][1] * inv0, zh, zl);
        *(uint32_t*)(g_ahi + zo0 + d) = zh;
        *(uint32_t*)(g_alo + zo0 + d) = zl;
        split2(oacc[nt][2] * inv1, oacc[nt][3] * inv1, zh, zl);
        *(uint32_t*)(g_ahi + zo1 + d) = zh;
        *(uint32_t*)(g_alo + zo1 + d) = zl;
    }
}

// ---------------------------------------------------------------------------
// Tensor-core projection GEMM: CTA 256x128, warp tile 64x64, 3-stage cp.async.
// ---------------------------------------------------------------------------
#define TK       32
#define NCHUNK   (DMODEL / TK)        // 32
#define ROWP     40
#define A_BYTES  (256 * ROWP * 2)     // 20480
#define B_BYTES  (128 * ROWP * 2)     // 10240
#define OFF_AH   0
#define OFF_AL   A_BYTES
#define OFF_BH   (2 * A_BYTES)
#define OFF_BL   (2 * A_BYTES + B_BYTES)
#define GSTAGE_BYTES (2 * A_BYTES + 2 * B_BYTES)   // 61440
#define GEMM_SMEM (3 * GSTAGE_BYTES)               // 184320

__global__ __launch_bounds__(256, 1)
void gemm_tc_kernel(const float* __restrict__ bias, float* __restrict__ C)
{
    extern __shared__ __align__(16) char smem[];
    const uint32_t sbase = smem_u32(smem);

    const int tid  = threadIdx.x;
    const int wid  = tid >> 5;
    const int lane = tid & 31;
    const int bm = blockIdx.y * 256;
    const int bn = blockIdx.x * 128;

    const int wm = (wid & 3) * 64;
    const int wn = (wid >> 2) * 64;
    const int g  = lane >> 2;
    const int t2 = (lane & 3) * 2;

    const uint32_t offA = (uint32_t)(((lane & 7) + ((lane >> 3) & 1) * 8) * ROWP
                                     + ((lane >> 4) & 1) * 8);
    const uint32_t offB = (uint32_t)(((lane & 7) + ((lane >> 4) & 1) * 8) * ROWP
                                     + ((lane >> 3) & 1) * 8);

    float acc[4][8][4];
    #pragma unroll
    for (int mt = 0; mt < 4; mt++)
        #pragma unroll
        for (int nt = 0; nt < 8; nt++)
            #pragma unroll
            for (int r = 0; r < 4; r++) acc[mt][nt][r] = 0.f;

    auto issue_chunk = [&](int kc, int stage) {
        const uint32_t sb = sbase + (uint32_t)stage * GSTAGE_BYTES;
        const int kb = kc * TK;
        #pragma unroll
        for (int rep = 0; rep < 4; rep++) {
            int idx = tid + rep * 256;
            int row = idx >> 2, seg = idx & 3;
            uint32_t d = sb + (uint32_t)(row * (ROWP * 2) + seg * 16);
            const size_t ga = (size_t)(bm + row) * DMODEL + kb + seg * 8;
            CP_ASYNC16(d + OFF_AH, g_ahi + ga);
            CP_ASYNC16(d + OFF_AL, g_alo + ga);
        }
        #pragma unroll
        for (int rep = 0; rep < 2; rep++) {
            int idx = tid + rep * 256;
            int row = idx >> 2, seg = idx & 3;
            uint32_t d = sb + (uint32_t)(row * (ROWP * 2) + seg * 16);
            const size_t gb = (size_t)(bn + row) * DMODEL + kb + seg * 8;
            CP_ASYNC16(d + OFF_BH, g_bhi + gb);
            CP_ASYNC16(d + OFF_BL, g_blo + gb);
        }
    };

    issue_chunk(0, 0);
    CP_COMMIT();
    issue_chunk(1, 1);
    CP_COMMIT();

    for (int kc = 0; kc < NCHUNK; kc++) {
        CP_WAIT1();
        __syncthreads();

        const uint32_t sb = sbase + (uint32_t)(kc % 3) * GSTAGE_BYTES;

        #pragma unroll
        for (int ks = 0; ks < 2; ks++) {
            const int k0 = ks * 16;
            uint32_t ah[4][4], al[4][4];
            #pragma unroll
            for (int mt = 0; mt < 4; mt++) {
                const uint32_t rel = (uint32_t)((wm + mt * 16) * ROWP + k0 + offA) * 2;
                ldsm4(ah[mt], sb + OFF_AH + rel);
                ldsm4(al[mt], sb + OFF_AL + rel);
            }
            #pragma unroll
            for (int ng = 0; ng < 4; ng++) {
                const uint32_t rel = (uint32_t)((wn + ng * 16) * ROWP + k0 + offB) * 2;
                uint32_t bh2[4], bl2[4];
                ldsm4(bh2, sb + OFF_BH + rel);
                ldsm4(bl2, sb + OFF_BL + rel);
                #pragma unroll
                for (int mt = 0; mt < 4; mt++) {
                    mma16816(acc[mt][2*ng],   ah[mt], bh2);
                    mma16816(acc[mt][2*ng],   ah[mt], bl2);
                    mma16816(acc[mt][2*ng],   al[mt], bh2);
                    mma16816(acc[mt][2*ng+1], ah[mt], bh2 + 2);
                    mma16816(acc[mt][2*ng+1], ah[mt], bl2 + 2);
                    mma16816(acc[mt][2*ng+1], al[mt], bh2 + 2);
                }
            }
        }

        if (kc + 2 < NCHUNK) issue_chunk(kc + 2, (kc + 2) % 3);
        CP_COMMIT();
    }

    #pragma unroll
    for (int mt = 0; mt < 4; mt++) {
        const int row0 = bm + wm + mt * 16 + g;
        #pragma unroll
        for (int nt = 0; nt < 8; nt++) {
            const int col0 = bn + wn + nt * 8 + t2;
            const float b0 = bias[col0], b1 = bias[col0 + 1];
            float2 o01 = { acc[mt][nt][0] + b0, acc[mt][nt][1] + b1 };
            float2 o23 = { acc[mt][nt][2] + b0, acc[mt][nt][3] + b1 };
            *(float2*)(C + (size_t)row0 * DMODEL + col0) = o01;
            *(float2*)(C + (size_t)(row0 + 8) * DMODEL + col0) = o23;
        }
    }
}

// ---------------------------------------------------------------------------
// Launch
// ---------------------------------------------------------------------------
extern "C" void kernel_launch(void* const* d_in, const int* in_sizes, int n_in,
                              void* d_out, int out_size)
{
    const float* residual = (const float*)d_in[0];
    const float* q        = (const float*)d_in[1];
    const float* k        = (const float*)d_in[2];
    const float* v        = (const float*)d_in[3];
    const float* W_O      = (const float*)d_in[4];
    const float* b_O      = (const float*)d_in[5];

    float* out = (float*)d_out;
    const int res_elems = BATCH * SEQ * DMODEL;

    // Merged pre-pass (residual copy + W/K/V conversion, all concurrent)
    prepass_kernel<<<PRE_TOTAL_B, 256>>>(residual, out, W_O, k, v);

    // Tensor-core attention -> g_ahi/g_alo (R8/R10/R12 config)
    cudaFuncSetAttribute(attn_tc_kernel,
                         cudaFuncAttributeMaxDynamicSharedMemorySize, ATT_SMEM);
    attn_tc_kernel<<<dim3(SEQ / 128, NHEADS, BATCH), 256, ATT_SMEM>>>(q);

    // Tensor-core projection (256x128 CTA, 64x64 warp tile)
    cudaFuncSetAttribute(gemm_tc_kernel,
                         cudaFuncAttributeMaxDynamicSharedMemorySize, GEMM_SMEM);
    gemm_tc_kernel<<<dim3(DMODEL / 128, (BATCH * SEQ) / 256), 256, GEMM_SMEM>>>(
        b_O, out + res_elems);
}